// round 8
// baseline (speedup 1.0000x reference)
#include <cuda_runtime.h>
#include <cuda_bf16.h>
#include <cstddef>
#include <cstdint>

// B=32, T=32768, K=N=8, D=256 — fused single-kernel GCAN loss with a
// cp.async producer pipeline feeding an mma consumer.
//   nlp = softplus(-x); p2 = sigmoid(x)^2
//   u = 4*nlp - x ; w = p2*x
//   A[k][n] = sum u*y ; W[k][n] = sum w*y   (mma.m16n8k16 bf16, u/w rows stacked)
//   S1[k] = sum (nlp+x) ; S2[k] = sum p2*(nlp+0.9x)
//   cost = (S1+A)/T ; assign_k = 0.75*(S2[k] - 0.8*W[k][col_k])

#define FULLMASK 0xffffffffu
#define CHUNKS 16
#define TPB_T 2048
#define SROWS 128          // t-rows per pipeline stage
#define NITER (TPB_T / SROWS)   // 16 stages per block
#define RSTRIDE 12         // padded words per row (bank-conflict-free gather)
#define SLOT 145           // 64 A + 64 W + 8 S1 + 8 S2 + 1 overlap

__device__ float gPart[32 * CHUNKS * SLOT];
__device__ float gGram[32 * 40];
__device__ float gOut[32];
__device__ unsigned gCntB[32];
__device__ unsigned gCntAll;

__constant__ int cPK[36] = {0,0,0,0,0,0,0,0, 1,1,1,1,1,1,1, 2,2,2,2,2,2,
                            3,3,3,3,3, 4,4,4,4, 5,5,5, 6,6, 7};
__constant__ int cPJ[36] = {0,1,2,3,4,5,6,7, 1,2,3,4,5,6,7, 2,3,4,5,6,7,
                            3,4,5,6,7, 4,5,6,7, 5,6,7, 6,7, 7};
__constant__ int cDiag[8] = {0,8,15,21,26,30,33,35};

__device__ __forceinline__ unsigned pk(float hi, float lo) {
    unsigned r;
    asm("cvt.rn.bf16x2.f32 %0, %1, %2;" : "=r"(r) : "f"(hi), "f"(lo));
    return r;
}

__device__ __forceinline__ void procE(float x, float& u, float& w,
                                      float& s1, float& s2) {
    float e = __expf(-x);
    float tt = 1.f + e;
    float nlp = __logf(tt);
    float r;
    asm("rcp.approx.ftz.f32 %0, %1;" : "=f"(r) : "f"(tt));
    float p2 = r * r;                     // sigmoid(x)^2
    u = fmaf(4.f, nlp, -x);
    w = p2 * x;
    s1 += nlp + x;
    s2 = fmaf(p2, fmaf(0.9f, x, nlp), s2);
}

__device__ __forceinline__ void cp16(uint32_t dst_smem, const void* src) {
    asm volatile("cp.async.cg.shared.global [%0], [%1], 16;"
                 :: "r"(dst_smem), "l"(src) : "memory");
}

__global__ void __launch_bounds__(256, 4)
fused_kernel(const float* __restrict__ logits, const float* __restrict__ labels,
             const float* __restrict__ olg, const float* __restrict__ otg,
             const float* __restrict__ att, const float* __restrict__ exist,
             float* __restrict__ out, int out_size) {
    __shared__ alignas(16) float xs[3][SROWS * RSTRIDE];   // 3 x 6KB
    __shared__ alignas(16) float ys[3][SROWS * RSTRIDE];   // 3 x 6KB
    __shared__ float sAcc[SLOT];
    __shared__ float red[SLOT];
    __shared__ float csh[64];
    __shared__ float dpv[256];
    __shared__ int   chx[256];
    __shared__ float snrm[8];
    __shared__ int   scol[8];
    __shared__ int   sIsLast;

    const int tid = threadIdx.x;
    const int b = blockIdx.y, c = blockIdx.x;
    if (tid < SLOT) sAcc[tid] = 0.f;

    const int t0 = c * TPB_T;
    const float* lg = logits + (size_t)b * 32768 * 8;
    const float* yb = labels + (size_t)b * 32768 * 8;

    // producer role: thread -> (row, 16B-half)
    const int pr = tid >> 1, ph = tid & 1;
    const float* gx0 = lg + (size_t)(t0 + pr) * 8 + ph * 4;
    const float* gy0 = yb + (size_t)(t0 + pr) * 8 + ph * 4;
    uint32_t dxs[3], dys[3];
#pragma unroll
    for (int s = 0; s < 3; s++) {
        dxs[s] = (uint32_t)__cvta_generic_to_shared(&xs[s][pr * RSTRIDE + ph * 4]);
        dys[s] = (uint32_t)__cvta_generic_to_shared(&ys[s][pr * RSTRIDE + ph * 4]);
    }

    // prefetch stages 0,1
    cp16(dxs[0], gx0);
    cp16(dys[0], gy0);
    asm volatile("cp.async.commit_group;" ::: "memory");
    cp16(dxs[1], gx0 + SROWS * 8);
    cp16(dys[1], gy0 + SROWS * 8);
    asm volatile("cp.async.commit_group;" ::: "memory");

    // ---- overlap MSE (overlaps with async prefetch) ----
    const float* ob = olg + (size_t)b * 32768 + t0;
    const float* tb = otg + (size_t)b * 32768 + t0;
    float ov = 0.f;
    for (int i = tid; i < TPB_T / 4; i += 256) {
        float4 o4 = reinterpret_cast<const float4*>(ob)[i];
        float4 t4 = reinterpret_cast<const float4*>(tb)[i];
        float d0 = o4.x - t4.x, d1 = o4.y - t4.y;
        float d2 = o4.z - t4.z, d3 = o4.w - t4.w;
        ov = fmaf(d0, d0, fmaf(d1, d1, fmaf(d2, d2, fmaf(d3, d3, ov))));
    }

    // consumer role
    const int wrp = tid >> 5, l = tid & 31;
    const int gid = l >> 2, tg = l & 3;
    const int w0 = (wrp * 16 + 2 * tg) * RSTRIDE + gid;   // base word in stage buf

    float c0 = 0.f, c1 = 0.f, c2 = 0.f, c3 = 0.f, s1 = 0.f, s2 = 0.f;

#pragma unroll 1
    for (int i = 0; i < NITER; i++) {
        if (i + 2 < NITER) {
            const float* gx = gx0 + (size_t)(i + 2) * SROWS * 8;
            const float* gy = gy0 + (size_t)(i + 2) * SROWS * 8;
            int sb = (i + 2) % 3;
            cp16(dxs[sb], gx);
            cp16(dys[sb], gy);
        }
        asm volatile("cp.async.commit_group;" ::: "memory");
        asm volatile("cp.async.wait_group 2;" ::: "memory");
        __syncthreads();

        const float* xb = xs[i % 3];
        const float* ybf = ys[i % 3];
        float x0 = xb[w0],                x1 = xb[w0 + RSTRIDE];
        float x2 = xb[w0 + 8 * RSTRIDE], x3 = xb[w0 + 9 * RSTRIDE];
        float y0 = ybf[w0],                y1 = ybf[w0 + RSTRIDE];
        float y2 = ybf[w0 + 8 * RSTRIDE], y3 = ybf[w0 + 9 * RSTRIDE];
        float u0, u1, u2, u3, ww0, ww1, ww2, ww3;
        procE(x0, u0, ww0, s1, s2);
        procE(x1, u1, ww1, s1, s2);
        procE(x2, u2, ww2, s1, s2);
        procE(x3, u3, ww3, s1, s2);
        unsigned a0 = pk(u1, u0),  a1 = pk(ww1, ww0);
        unsigned a2 = pk(u3, u2),  a3 = pk(ww3, ww2);
        unsigned b0 = pk(y1, y0),  b1 = pk(y3, y2);
        asm("mma.sync.aligned.m16n8k16.row.col.f32.bf16.bf16.f32 "
            "{%0,%1,%2,%3}, {%4,%5,%6,%7}, {%8,%9}, {%0,%1,%2,%3};"
            : "+f"(c0), "+f"(c1), "+f"(c2), "+f"(c3)
            : "r"(a0), "r"(a1), "r"(a2), "r"(a3), "r"(b0), "r"(b1));
        __syncthreads();
    }

    s1 += __shfl_xor_sync(FULLMASK, s1, 1);
    s1 += __shfl_xor_sync(FULLMASK, s1, 2);
    s2 += __shfl_xor_sync(FULLMASK, s2, 1);
    s2 += __shfl_xor_sync(FULLMASK, s2, 2);
#pragma unroll
    for (int off = 16; off >= 1; off >>= 1) ov += __shfl_down_sync(FULLMASK, ov, off);

    atomicAdd(&sAcc[gid * 8 + 2 * tg],          c0);
    atomicAdd(&sAcc[gid * 8 + 2 * tg + 1],      c1);
    atomicAdd(&sAcc[64 + gid * 8 + 2 * tg],     c2);
    atomicAdd(&sAcc[64 + gid * 8 + 2 * tg + 1], c3);
    if (tg == 0) {
        atomicAdd(&sAcc[128 + gid], s1);
        atomicAdd(&sAcc[136 + gid], s2);
    }
    if (l == 0) atomicAdd(&sAcc[144], ov);
    __syncthreads();

    if (tid < SLOT) gPart[(b * CHUNKS + c) * SLOT + tid] = sAcc[tid];

    // ---- gram + existence: chunk-0 blocks, read attractors from global ----
    if (c == 0) {
        const float* ab = att + (size_t)b * 2048;
        for (int p = wrp; p < 36; p += 8) {
            const float* rk = ab + cPK[p] * 256 + l;
            const float* rj = ab + cPJ[p] * 256 + l;
            float s = 0.f;
#pragma unroll
            for (int m = 0; m < 8; m++) s = fmaf(rk[32 * m], rj[32 * m], s);
#pragma unroll
            for (int off = 16; off >= 1; off >>= 1) s += __shfl_down_sync(FULLMASK, s, off);
            if (l == 0) gGram[b * 40 + p] = s;
        }
        if (wrp == 0) {
            float v = 0.f;
            if (l < 8) {
                float e  = exist[b * 8 + l];
                float ll = __logf(1.f + __expf(-fabsf(e)));
                float spn = ll + fmaxf(-e, 0.f);
                float spp = ll + fmaxf(e, 0.f);
                v = 4.5f * spn + 0.1f * spp;
            }
            v += __shfl_down_sync(FULLMASK, v, 4);
            v += __shfl_down_sync(FULLMASK, v, 2);
            v += __shfl_down_sync(FULLMASK, v, 1);
            if (l == 0) gGram[b * 40 + 36] = v;
        }
    }

    // ---- last-arrival per batch: barrier -> fence -> atomic ----
    __syncthreads();
    if (tid == 0) {
        __threadfence();
        unsigned old = atomicAdd(&gCntB[b], 1u);
        sIsLast = (((old + 1u) & 15u) == 0u) ? 1 : 0;
    }
    __syncthreads();
    if (!sIsLast) return;
    __threadfence();

    if (tid < SLOT) {
        float s = 0.f;
#pragma unroll
        for (int cc = 0; cc < CHUNKS; cc++) s += gPart[(b * CHUNKS + cc) * SLOT + tid];
        red[tid] = s;
    }
    __syncthreads();
    if (tid >= 32) return;

    // ======== warp-0 epilogue, lane-parallel ========
    const int lane = tid;
    for (int e = lane; e < 64; e += 32) {
        int k = e >> 3;
        float cc = (red[128 + k] + red[e]) * (1.f / 32768.f);
        if (!(fabsf(cc) <= 1e30f)) cc = 100.f;
        csh[e] = cc;
    }
    if (lane < 8) snrm[lane] = fmaxf(sqrtf(gGram[b * 40 + cDiag[lane]]), 1e-12f);
    if (lane == 0) dpv[0] = 0.f;
    __syncwarp();

    float o = 0.f, ct = 0.f;
    for (int p = lane; p < 36; p += 32) {
        float s = gGram[b * 40 + p] / (snrm[cPK[p]] * snrm[cPJ[p]]);
        if (cPK[p] == cPJ[p]) { float d = s - 1.f; o += d * d; }
        else { o += 2.f * s * s; ct += 2.f * fmaxf(s + 0.5f, 0.f); }
    }
#pragma unroll
    for (int off = 16; off >= 1; off >>= 1) {
        o  += __shfl_down_sync(FULLMASK, o,  off);
        ct += __shfl_down_sync(FULLMASK, ct, off);
    }

    for (int r = 1; r <= 8; r++) {
        __syncwarp();
#pragma unroll
        for (int q = 0; q < 8; q++) {
            int m = lane * 8 + q;
            if (m >= 1 && __popc(m) == r) {
                float best = 1e30f; int bn = 0;
#pragma unroll
                for (int n = 0; n < 8; n++) {
                    if (m & (1 << n)) {
                        float v = dpv[m ^ (1 << n)] + csh[(r - 1) * 8 + n];
                        if (v < best) { best = v; bn = n; }
                    }
                }
                dpv[m] = best; chx[m] = bn;
            }
        }
    }
    __syncwarp();
    if (lane == 0) {
        int mask = 255;
        for (int r = 7; r >= 0; --r) { int n = chx[mask]; scol[r] = n; mask ^= (1 << n); }
    }
    __syncwarp();

    float asn = 0.f;
    if (lane < 8)
        asn = 0.75f * (red[136 + lane] - 0.8f * red[64 + lane * 8 + scol[lane]]);
    asn += __shfl_down_sync(FULLMASK, asn, 4);
    asn += __shfl_down_sync(FULLMASK, asn, 2);
    asn += __shfl_down_sync(FULLMASK, asn, 1);

    int lastAll = 0;
    if (lane == 0) {
        float exq = gGram[b * 40 + 36];
        float contrib = asn * (1.f / 8388608.f)
                      + exq * (1.f / 256.f)
                      + 0.1f * o  * (1.f / 2048.f)
                      + 0.1f * ct * (1.f / 1792.f)
                      + 0.5f * red[144] * (1.f / 1048576.f);
        gOut[b] = contrib;
        __threadfence();
        unsigned old2 = atomicAdd(&gCntAll, 1u);
        lastAll = (((old2 + 1u) & 31u) == 0u) ? 1 : 0;
    }
    lastAll = __shfl_sync(FULLMASK, lastAll, 0);
    if (!lastAll) return;
    __threadfence();

    float v = gOut[lane];
#pragma unroll
    for (int off = 16; off >= 1; off >>= 1) v += __shfl_down_sync(FULLMASK, v, off);
    float total = __shfl_sync(FULLMASK, v, 0);
    for (int i = lane; i < out_size; i += 32) out[i] = total;
}

extern "C" void kernel_launch(void* const* d_in, const int* in_sizes, int n_in,
                              void* d_out, int out_size) {
    const float* logits    = (const float*)d_in[0];
    const float* existence = (const float*)d_in[1];
    const float* attract   = (const float*)d_in[2];
    const float* labels    = (const float*)d_in[3];
    const float* olg       = (const float*)d_in[4];
    const float* otg       = (const float*)d_in[5];
    float* out = (float*)d_out;

    dim3 grid(CHUNKS, 32);
    fused_kernel<<<grid, 256>>>(logits, labels, olg, otg,
                                attract, existence, out, out_size);
}

// round 9
// speedup vs baseline: 1.0546x; 1.0546x over previous
#include <cuda_runtime.h>
#include <cuda_bf16.h>
#include <cstddef>
#include <cstdint>

// B=32, T=32768, K=N=8, D=256 — fused single-kernel GCAN loss.
// Per-WARP cp.async pipeline (no block barriers in the main loop) feeding mma.
//   nlp = softplus(-x); p2 = sigmoid(x)^2
//   u = 4*nlp - x ; w = p2*x
//   A[k][n] = sum u*y ; W[k][n] = sum w*y   (mma.m16n8k16 bf16, u/w rows stacked)
//   S1[k] = sum (nlp+x) ; S2[k] = sum p2*(nlp+0.9x)
//   cost = (S1+A)/T ; assign_k = 0.75*(S2[k] - 0.8*W[k][col_k])

#define FULLMASK 0xffffffffu
#define CHUNKS 16
#define TPB_T 2048
#define WTILES 16          // tiles per warp (16 rows each, warp span = 256 rows)
#define RS 12              // padded words per row (conflict-free LDS)
#define TILEW (16 * RS)    // 192 words per tile per tensor
#define SLOT 145           // 64 A + 64 W + 8 S1 + 8 S2 + 1 overlap

__device__ float gPart[32 * CHUNKS * SLOT];
__device__ float gGram[32 * 40];
__device__ float gOut[32];
__device__ unsigned gCntB[32];
__device__ unsigned gCntAll;

__constant__ int cPK[36] = {0,0,0,0,0,0,0,0, 1,1,1,1,1,1,1, 2,2,2,2,2,2,
                            3,3,3,3,3, 4,4,4,4, 5,5,5, 6,6, 7};
__constant__ int cPJ[36] = {0,1,2,3,4,5,6,7, 1,2,3,4,5,6,7, 2,3,4,5,6,7,
                            3,4,5,6,7, 4,5,6,7, 5,6,7, 6,7, 7};
__constant__ int cDiag[8] = {0,8,15,21,26,30,33,35};

__device__ __forceinline__ unsigned pk(float hi, float lo) {
    unsigned r;
    asm("cvt.rn.bf16x2.f32 %0, %1, %2;" : "=r"(r) : "f"(hi), "f"(lo));
    return r;
}

__device__ __forceinline__ void procE(float x, float& u, float& w,
                                      float& s1, float& s2) {
    float e = __expf(-x);
    float tt = 1.f + e;
    float nlp = __logf(tt);
    float r;
    asm("rcp.approx.ftz.f32 %0, %1;" : "=f"(r) : "f"(tt));
    float p2 = r * r;                     // sigmoid(x)^2
    u = fmaf(4.f, nlp, -x);
    w = p2 * x;
    s1 += nlp + x;
    s2 = fmaf(p2, fmaf(0.9f, x, nlp), s2);
}

__device__ __forceinline__ void cp16(uint32_t dst_smem, const void* src) {
    asm volatile("cp.async.cg.shared.global [%0], [%1], 16;"
                 :: "r"(dst_smem), "l"(src) : "memory");
}

__global__ void __launch_bounds__(256, 4)
fused_kernel(const float* __restrict__ logits, const float* __restrict__ labels,
             const float* __restrict__ olg, const float* __restrict__ otg,
             const float* __restrict__ att, const float* __restrict__ exist,
             float* __restrict__ out, int out_size) {
    // per-warp 3-stage rings: [warp][stage][192]
    __shared__ alignas(16) float xs[8][3][TILEW];
    __shared__ alignas(16) float ys[8][3][TILEW];
    __shared__ float sAcc[SLOT];
    __shared__ float red[SLOT];
    __shared__ float csh[64];
    __shared__ float dpv[256];
    __shared__ int   chx[256];
    __shared__ float snrm[8];
    __shared__ int   scol[8];
    __shared__ int   sIsLast;

    const int tid = threadIdx.x;
    const int b = blockIdx.y, c = blockIdx.x;
    if (tid < SLOT) sAcc[tid] = 0.f;

    const int t0 = c * TPB_T;
    const float* lg = logits + (size_t)b * 32768 * 8;
    const float* yb = labels + (size_t)b * 32768 * 8;

    const int wrp = tid >> 5, l = tid & 31;
    const int gid = l >> 2, tg = l & 3;

    // producer: lane -> (row pr, 16B half ph) of this warp's 16-row tile
    const int pr = l >> 1, ph = l & 1;
    const float* gx0 = lg + (size_t)(t0 + wrp * 256 + pr) * 8 + ph * 4;
    const float* gy0 = yb + (size_t)(t0 + wrp * 256 + pr) * 8 + ph * 4;
    uint32_t dxs[3], dys[3];
#pragma unroll
    for (int s = 0; s < 3; s++) {
        dxs[s] = (uint32_t)__cvta_generic_to_shared(&xs[wrp][s][pr * RS + ph * 4]);
        dys[s] = (uint32_t)__cvta_generic_to_shared(&ys[wrp][s][pr * RS + ph * 4]);
    }

    // prefetch tiles 0,1 (one group each)
    cp16(dxs[0], gx0);
    cp16(dys[0], gy0);
    asm volatile("cp.async.commit_group;" ::: "memory");
    cp16(dxs[1], gx0 + 16 * 8);
    cp16(dys[1], gy0 + 16 * 8);
    asm volatile("cp.async.commit_group;" ::: "memory");

    // ---- overlap MSE (overlaps the prefetch) ----
    const float* ob = olg + (size_t)b * 32768 + t0;
    const float* tb = otg + (size_t)b * 32768 + t0;
    float ov = 0.f;
    for (int i = tid; i < TPB_T / 4; i += 256) {
        float4 o4 = reinterpret_cast<const float4*>(ob)[i];
        float4 t4 = reinterpret_cast<const float4*>(tb)[i];
        float d0 = o4.x - t4.x, d1 = o4.y - t4.y;
        float d2 = o4.z - t4.z, d3 = o4.w - t4.w;
        ov = fmaf(d0, d0, fmaf(d1, d1, fmaf(d2, d2, fmaf(d3, d3, ov))));
    }

    // consume offsets within a tile (words); conflict-free with RS=12
    const int q0 = (2 * tg)     * RS + gid;
    const int q1 = (2 * tg + 1) * RS + gid;
    const int q2 = (2 * tg + 8) * RS + gid;
    const int q3 = (2 * tg + 9) * RS + gid;

    float c0 = 0.f, c1 = 0.f, c2 = 0.f, c3 = 0.f, s1 = 0.f, s2 = 0.f;

#pragma unroll 1
    for (int i = 0; i < WTILES; i++) {
        if (i + 2 < WTILES) {
            int sb = (i + 2) % 3;
            cp16(dxs[sb], gx0 + (size_t)(i + 2) * 16 * 8);
            cp16(dys[sb], gy0 + (size_t)(i + 2) * 16 * 8);
        }
        asm volatile("cp.async.commit_group;" ::: "memory");
        asm volatile("cp.async.wait_group 2;" ::: "memory");
        __syncwarp();     // cross-lane visibility of this warp's completed copies

        const float* xb  = xs[wrp][i % 3];
        const float* ybf = ys[wrp][i % 3];
        float x0 = xb[q0], x1 = xb[q1], x2 = xb[q2], x3 = xb[q3];
        float y0 = ybf[q0], y1 = ybf[q1], y2 = ybf[q2], y3 = ybf[q3];
        float u0, u1, u2, u3, w0, w1, w2, w3;
        procE(x0, u0, w0, s1, s2);
        procE(x1, u1, w1, s1, s2);
        procE(x2, u2, w2, s1, s2);
        procE(x3, u3, w3, s1, s2);
        unsigned a0 = pk(u1, u0), a1 = pk(w1, w0);
        unsigned a2 = pk(u3, u2), a3 = pk(w3, w2);
        unsigned b0 = pk(y1, y0), b1 = pk(y3, y2);
        asm("mma.sync.aligned.m16n8k16.row.col.f32.bf16.bf16.f32 "
            "{%0,%1,%2,%3}, {%4,%5,%6,%7}, {%8,%9}, {%0,%1,%2,%3};"
            : "+f"(c0), "+f"(c1), "+f"(c2), "+f"(c3)
            : "r"(a0), "r"(a1), "r"(a2), "r"(a3), "r"(b0), "r"(b1));
        __syncwarp();     // all lanes done reading stage i before it is rewritten
    }

    s1 += __shfl_xor_sync(FULLMASK, s1, 1);
    s1 += __shfl_xor_sync(FULLMASK, s1, 2);
    s2 += __shfl_xor_sync(FULLMASK, s2, 1);
    s2 += __shfl_xor_sync(FULLMASK, s2, 2);
#pragma unroll
    for (int off = 16; off >= 1; off >>= 1) ov += __shfl_down_sync(FULLMASK, ov, off);

    __syncthreads();   // sAcc init visible; all warps ready to accumulate
    atomicAdd(&sAcc[gid * 8 + 2 * tg],          c0);
    atomicAdd(&sAcc[gid * 8 + 2 * tg + 1],      c1);
    atomicAdd(&sAcc[64 + gid * 8 + 2 * tg],     c2);
    atomicAdd(&sAcc[64 + gid * 8 + 2 * tg + 1], c3);
    if (tg == 0) {
        atomicAdd(&sAcc[128 + gid], s1);
        atomicAdd(&sAcc[136 + gid], s2);
    }
    if (l == 0) atomicAdd(&sAcc[144], ov);
    __syncthreads();

    if (tid < SLOT) gPart[(b * CHUNKS + c) * SLOT + tid] = sAcc[tid];

    // ---- gram + existence: chunk-0 blocks, attractors straight from global ----
    if (c == 0) {
        const float* ab = att + (size_t)b * 2048;
        for (int p = wrp; p < 36; p += 8) {
            const float* rk = ab + cPK[p] * 256 + l;
            const float* rj = ab + cPJ[p] * 256 + l;
            float s = 0.f;
#pragma unroll
            for (int m = 0; m < 8; m++) s = fmaf(rk[32 * m], rj[32 * m], s);
#pragma unroll
            for (int off = 16; off >= 1; off >>= 1) s += __shfl_down_sync(FULLMASK, s, off);
            if (l == 0) gGram[b * 40 + p] = s;
        }
        if (wrp == 0) {
            float v = 0.f;
            if (l < 8) {
                float e  = exist[b * 8 + l];
                float ll = __logf(1.f + __expf(-fabsf(e)));
                float spn = ll + fmaxf(-e, 0.f);
                float spp = ll + fmaxf(e, 0.f);
                v = 4.5f * spn + 0.1f * spp;
            }
            v += __shfl_down_sync(FULLMASK, v, 4);
            v += __shfl_down_sync(FULLMASK, v, 2);
            v += __shfl_down_sync(FULLMASK, v, 1);
            if (l == 0) gGram[b * 40 + 36] = v;
        }
    }

    // ---- last-arrival per batch: barrier -> fence -> atomic ----
    __syncthreads();
    if (tid == 0) {
        __threadfence();
        unsigned old = atomicAdd(&gCntB[b], 1u);
        sIsLast = (((old + 1u) & 15u) == 0u) ? 1 : 0;
    }
    __syncthreads();
    if (!sIsLast) return;
    __threadfence();

    if (tid < SLOT) {
        float s = 0.f;
#pragma unroll
        for (int cc = 0; cc < CHUNKS; cc++) s += gPart[(b * CHUNKS + cc) * SLOT + tid];
        red[tid] = s;
    }
    __syncthreads();
    if (tid >= 32) return;

    // ======== warp-0 epilogue, lane-parallel ========
    const int lane = tid;
    for (int e = lane; e < 64; e += 32) {
        int k = e >> 3;
        float cc = (red[128 + k] + red[e]) * (1.f / 32768.f);
        if (!(fabsf(cc) <= 1e30f)) cc = 100.f;
        csh[e] = cc;
    }
    if (lane < 8) snrm[lane] = fmaxf(sqrtf(gGram[b * 40 + cDiag[lane]]), 1e-12f);
    if (lane == 0) dpv[0] = 0.f;
    __syncwarp();

    float o = 0.f, ct = 0.f;
    for (int p = lane; p < 36; p += 32) {
        float s = gGram[b * 40 + p] / (snrm[cPK[p]] * snrm[cPJ[p]]);
        if (cPK[p] == cPJ[p]) { float d = s - 1.f; o += d * d; }
        else { o += 2.f * s * s; ct += 2.f * fmaxf(s + 0.5f, 0.f); }
    }
#pragma unroll
    for (int off = 16; off >= 1; off >>= 1) {
        o  += __shfl_down_sync(FULLMASK, o,  off);
        ct += __shfl_down_sync(FULLMASK, ct, off);
    }

    for (int r = 1; r <= 8; r++) {
        __syncwarp();
#pragma unroll
        for (int q = 0; q < 8; q++) {
            int m = lane * 8 + q;
            if (m >= 1 && __popc(m) == r) {
                float best = 1e30f; int bn = 0;
#pragma unroll
                for (int n = 0; n < 8; n++) {
                    if (m & (1 << n)) {
                        float v = dpv[m ^ (1 << n)] + csh[(r - 1) * 8 + n];
                        if (v < best) { best = v; bn = n; }
                    }
                }
                dpv[m] = best; chx[m] = bn;
            }
        }
    }
    __syncwarp();
    if (lane == 0) {
        int mask = 255;
        for (int r = 7; r >= 0; --r) { int n = chx[mask]; scol[r] = n; mask ^= (1 << n); }
    }
    __syncwarp();

    float asn = 0.f;
    if (lane < 8)
        asn = 0.75f * (red[136 + lane] - 0.8f * red[64 + lane * 8 + scol[lane]]);
    asn += __shfl_down_sync(FULLMASK, asn, 4);
    asn += __shfl_down_sync(FULLMASK, asn, 2);
    asn += __shfl_down_sync(FULLMASK, asn, 1);

    int lastAll = 0;
    if (lane == 0) {
        float exq = gGram[b * 40 + 36];
        float contrib = asn * (1.f / 8388608.f)
                      + exq * (1.f / 256.f)
                      + 0.1f * o  * (1.f / 2048.f)
                      + 0.1f * ct * (1.f / 1792.f)
                      + 0.5f * red[144] * (1.f / 1048576.f);
        gOut[b] = contrib;
        __threadfence();
        unsigned old2 = atomicAdd(&gCntAll, 1u);
        lastAll = (((old2 + 1u) & 31u) == 0u) ? 1 : 0;
    }
    lastAll = __shfl_sync(FULLMASK, lastAll, 0);
    if (!lastAll) return;
    __threadfence();

    float v = gOut[lane];
#pragma unroll
    for (int off = 16; off >= 1; off >>= 1) v += __shfl_down_sync(FULLMASK, v, off);
    float total = __shfl_sync(FULLMASK, v, 0);
    for (int i = lane; i < out_size; i += 32) out[i] = total;
}

extern "C" void kernel_launch(void* const* d_in, const int* in_sizes, int n_in,
                              void* d_out, int out_size) {
    const float* logits    = (const float*)d_in[0];
    const float* existence = (const float*)d_in[1];
    const float* attract   = (const float*)d_in[2];
    const float* labels    = (const float*)d_in[3];
    const float* olg       = (const float*)d_in[4];
    const float* otg       = (const float*)d_in[5];
    float* out = (float*)d_out;

    dim3 grid(CHUNKS, 32);
    fused_kernel<<<grid, 256>>>(logits, labels, olg, otg,
                                attract, existence, out, out_size);
}

// round 10
// speedup vs baseline: 1.1887x; 1.1271x over previous
#include <cuda_runtime.h>
#include <cuda_bf16.h>
#include <cstddef>

// B=32, T=32768, K=N=8, D=256.
// Two kernels: balanced streaming mma pass (592 blocks, 1024-row tiles),
// then a lean per-batch epilogue (32 blocks, last one writes out).
//   nlp = softplus(-x); p2 = sigmoid(x)^2
//   u = 4*nlp - x ; w = p2*x
//   A[k][n] = sum u*y ; W[k][n] = sum w*y   (mma.m16n8k16 bf16, u/w rows stacked)
//   S1[k] = sum (nlp+x) ; S2[k] = sum p2*(nlp+0.9x)
//   cost = (S1+A)/T ; assign_k = 0.75*(S2[k] - 0.8*W[k][col_k])

#define FULLMASK 0xffffffffu
#define NTILES 1024        // 32 batches x 32 tiles of 1024 rows
#define GRID1 592          // 148 SMs x 4 CTAs, single balanced wave
#define SLOT 145           // 64 A + 64 W + 8 S1 + 8 S2 + 1 overlap

__device__ float gPart[NTILES * SLOT];
__device__ float gOut[32];
__device__ unsigned gCntAll;

__constant__ int cPK[36] = {0,0,0,0,0,0,0,0, 1,1,1,1,1,1,1, 2,2,2,2,2,2,
                            3,3,3,3,3, 4,4,4,4, 5,5,5, 6,6, 7};
__constant__ int cPJ[36] = {0,1,2,3,4,5,6,7, 1,2,3,4,5,6,7, 2,3,4,5,6,7,
                            3,4,5,6,7, 4,5,6,7, 5,6,7, 6,7, 7};
__constant__ int cDiag[8] = {0,8,15,21,26,30,33,35};

__device__ __forceinline__ unsigned pk(float hi, float lo) {
    unsigned r;
    asm("cvt.rn.bf16x2.f32 %0, %1, %2;" : "=r"(r) : "f"(hi), "f"(lo));
    return r;
}

__device__ __forceinline__ void procE(float x, float& u, float& w,
                                      float& s1, float& s2) {
    float e = __expf(-x);
    float tt = 1.f + e;
    float nlp = __logf(tt);
    float r;
    asm("rcp.approx.ftz.f32 %0, %1;" : "=f"(r) : "f"(tt));
    float p2 = r * r;                     // sigmoid(x)^2
    u = fmaf(4.f, nlp, -x);
    w = p2 * x;
    s1 += nlp + x;
    s2 = fmaf(p2, fmaf(0.9f, x, nlp), s2);
}

__global__ void __launch_bounds__(256, 4)
main_kernel(const float* __restrict__ logits, const float* __restrict__ labels,
            const float* __restrict__ olg, const float* __restrict__ otg) {
    __shared__ float sAcc[SLOT];
    const int tid = threadIdx.x;
    const int wrp = tid >> 5, l = tid & 31;
    const int gid = l >> 2, tg = l & 3;
    const int o0 = 16 * tg, o1 = o0 + 8, o2 = o0 + 64, o3 = o0 + 72;

#pragma unroll 1
    for (int tt = 0; tt < 2; tt++) {
        const int tau = blockIdx.x + tt * GRID1;
        if (tau >= NTILES) break;
        const int b = tau >> 5;
        const int t0 = (tau & 31) << 10;          // 1024-row tile

        if (tid < SLOT) sAcc[tid] = 0.f;
        __syncthreads();

        // ---- overlap MSE: exactly one float4 pair per thread ----
        const float* ob = olg + (size_t)b * 32768 + t0;
        const float* tb = otg + (size_t)b * 32768 + t0;
        float4 o4 = reinterpret_cast<const float4*>(ob)[tid];
        float4 t4 = reinterpret_cast<const float4*>(tb)[tid];
        float d0 = o4.x - t4.x, d1 = o4.y - t4.y;
        float d2 = o4.z - t4.z, d3 = o4.w - t4.w;
        float ov = fmaf(d0, d0, fmaf(d1, d1, fmaf(d2, d2, d3 * d3)));

        // ---- mma streaming: warp covers 128 rows as 8 steps of 16 ----
        const float* xp = logits + ((size_t)b * 32768 + t0 + wrp * 128) * 8 + gid;
        const float* yp = labels + ((size_t)b * 32768 + t0 + wrp * 128) * 8 + gid;

        float c0 = 0.f, c1 = 0.f, c2 = 0.f, c3 = 0.f, s1 = 0.f, s2 = 0.f;

#pragma unroll 4
        for (int i = 0; i < 8; i++) {
            const int base = i * 128;
            float x0 = xp[base + o0], x1 = xp[base + o1];
            float x2 = xp[base + o2], x3 = xp[base + o3];
            float y0 = yp[base + o0], y1 = yp[base + o1];
            float y2 = yp[base + o2], y3 = yp[base + o3];
            float u0, u1, u2, u3, w0, w1, w2, w3;
            procE(x0, u0, w0, s1, s2);
            procE(x1, u1, w1, s1, s2);
            procE(x2, u2, w2, s1, s2);
            procE(x3, u3, w3, s1, s2);
            unsigned a0 = pk(u1, u0), a1 = pk(w1, w0);
            unsigned a2 = pk(u3, u2), a3 = pk(w3, w2);
            unsigned b0 = pk(y1, y0), b1 = pk(y3, y2);
            asm("mma.sync.aligned.m16n8k16.row.col.f32.bf16.bf16.f32 "
                "{%0,%1,%2,%3}, {%4,%5,%6,%7}, {%8,%9}, {%0,%1,%2,%3};"
                : "+f"(c0), "+f"(c1), "+f"(c2), "+f"(c3)
                : "r"(a0), "r"(a1), "r"(a2), "r"(a3), "r"(b0), "r"(b1));
        }

        s1 += __shfl_xor_sync(FULLMASK, s1, 1);
        s1 += __shfl_xor_sync(FULLMASK, s1, 2);
        s2 += __shfl_xor_sync(FULLMASK, s2, 1);
        s2 += __shfl_xor_sync(FULLMASK, s2, 2);
#pragma unroll
        for (int off = 16; off >= 1; off >>= 1) ov += __shfl_down_sync(FULLMASK, ov, off);

        atomicAdd(&sAcc[gid * 8 + 2 * tg],          c0);
        atomicAdd(&sAcc[gid * 8 + 2 * tg + 1],      c1);
        atomicAdd(&sAcc[64 + gid * 8 + 2 * tg],     c2);
        atomicAdd(&sAcc[64 + gid * 8 + 2 * tg + 1], c3);
        if (tg == 0) {
            atomicAdd(&sAcc[128 + gid], s1);
            atomicAdd(&sAcc[136 + gid], s2);
        }
        if (l == 0) atomicAdd(&sAcc[144], ov);
        __syncthreads();

        if (tid < SLOT) gPart[tau * SLOT + tid] = sAcc[tid];
        __syncthreads();   // gPart read of sAcc done before next tile re-zeroes
    }
}

// Per-batch epilogue: 32 tile-partial reduction + gram + subset-DP + existence.
// Last block (never-reset counter) sums gOut and writes the output.
__global__ void __launch_bounds__(256)
batch_kernel(const float* __restrict__ att, const float* __restrict__ exist,
             float* __restrict__ out, int out_size) {
    __shared__ float red[SLOT];
    __shared__ float gr[37];     // 36 gram upper-tri + [36] existence
    __shared__ float csh[64];
    __shared__ float dpv[256];
    __shared__ int   chx[256];
    __shared__ float snrm[8];
    __shared__ int   scol[8];
    const int b = blockIdx.x, tid = threadIdx.x;
    const int wrp = tid >> 5, l = tid & 31;

    if (tid < SLOT) {
        float s = 0.f;
#pragma unroll
        for (int c = 0; c < 32; c++) s += gPart[(b * 32 + c) * SLOT + tid];
        red[tid] = s;
    }

    // gram: warp-per-pair straight from global (L2-resident)
    const float* ab = att + (size_t)b * 2048;
    for (int p = wrp; p < 36; p += 8) {
        const float* rk = ab + cPK[p] * 256 + l;
        const float* rj = ab + cPJ[p] * 256 + l;
        float s = 0.f;
#pragma unroll
        for (int m = 0; m < 8; m++) s = fmaf(rk[32 * m], rj[32 * m], s);
#pragma unroll
        for (int off = 16; off >= 1; off >>= 1) s += __shfl_down_sync(FULLMASK, s, off);
        if (l == 0) gr[p] = s;
    }
    if (wrp == 1) {               // existence row on warp 1 (parallel with gram)
        float v = 0.f;
        if (l < 8) {
            float e  = exist[b * 8 + l];
            float ll = __logf(1.f + __expf(-fabsf(e)));
            float spn = ll + fmaxf(-e, 0.f);
            float spp = ll + fmaxf(e, 0.f);
            v = 4.5f * spn + 0.1f * spp;
        }
        v += __shfl_down_sync(FULLMASK, v, 4);
        v += __shfl_down_sync(FULLMASK, v, 2);
        v += __shfl_down_sync(FULLMASK, v, 1);
        if (l == 0) gr[36] = v;
    }
    __syncthreads();
    if (tid >= 32) return;

    // ---- warp-0 lane-parallel finalize ----
    const int lane = tid;
    for (int e = lane; e < 64; e += 32) {
        int k = e >> 3;
        float cc = (red[128 + k] + red[e]) * (1.f / 32768.f);
        if (!(fabsf(cc) <= 1e30f)) cc = 100.f;
        csh[e] = cc;
    }
    if (lane < 8) snrm[lane] = fmaxf(sqrtf(gr[cDiag[lane]]), 1e-12f);
    if (lane == 0) dpv[0] = 0.f;
    __syncwarp();

    float o = 0.f, ct = 0.f;
    for (int p = lane; p < 36; p += 32) {
        float s = gr[p] / (snrm[cPK[p]] * snrm[cPJ[p]]);
        if (cPK[p] == cPJ[p]) { float d = s - 1.f; o += d * d; }
        else { o += 2.f * s * s; ct += 2.f * fmaxf(s + 0.5f, 0.f); }
    }
#pragma unroll
    for (int off = 16; off >= 1; off >>= 1) {
        o  += __shfl_down_sync(FULLMASK, o,  off);
        ct += __shfl_down_sync(FULLMASK, ct, off);
    }

    // subset-DP: lane owns masks lane*8..lane*8+7
    for (int r = 1; r <= 8; r++) {
        __syncwarp();
#pragma unroll
        for (int q = 0; q < 8; q++) {
            int m = lane * 8 + q;
            if (m >= 1 && __popc(m) == r) {
                float best = 1e30f; int bn = 0;
#pragma unroll
                for (int n = 0; n < 8; n++) {
                    if (m & (1 << n)) {
                        float v = dpv[m ^ (1 << n)] + csh[(r - 1) * 8 + n];
                        if (v < best) { best = v; bn = n; }
                    }
                }
                dpv[m] = best; chx[m] = bn;
            }
        }
    }
    __syncwarp();
    if (lane == 0) {
        int mask = 255;
        for (int r = 7; r >= 0; --r) { int n = chx[mask]; scol[r] = n; mask ^= (1 << n); }
    }
    __syncwarp();

    float asn = 0.f;
    if (lane < 8)
        asn = 0.75f * (red[136 + lane] - 0.8f * red[64 + lane * 8 + scol[lane]]);
    asn += __shfl_down_sync(FULLMASK, asn, 4);
    asn += __shfl_down_sync(FULLMASK, asn, 2);
    asn += __shfl_down_sync(FULLMASK, asn, 1);

    int lastAll = 0;
    if (lane == 0) {
        float contrib = asn * (1.f / 8388608.f)          // assign mean (B*T*K)
                      + gr[36] * (1.f / 256.f)           // exist mean
                      + 0.1f * o  * (1.f / 2048.f)       // ortho mean
                      + 0.1f * ct * (1.f / 1792.f)       // contrast
                      + 0.5f * red[144] * (1.f / 1048576.f); // overlap mean
        gOut[b] = contrib;
        __threadfence();
        unsigned old = atomicAdd(&gCntAll, 1u);
        lastAll = (((old + 1u) & 31u) == 0u) ? 1 : 0;
    }
    lastAll = __shfl_sync(FULLMASK, lastAll, 0);
    if (!lastAll) return;
    __threadfence();

    float v = gOut[lane];
#pragma unroll
    for (int off = 16; off >= 1; off >>= 1) v += __shfl_down_sync(FULLMASK, v, off);
    float total = __shfl_sync(FULLMASK, v, 0);
    for (int i = lane; i < out_size; i += 32) out[i] = total;
}

extern "C" void kernel_launch(void* const* d_in, const int* in_sizes, int n_in,
                              void* d_out, int out_size) {
    const float* logits    = (const float*)d_in[0];
    const float* existence = (const float*)d_in[1];
    const float* attract   = (const float*)d_in[2];
    const float* labels    = (const float*)d_in[3];
    const float* olg       = (const float*)d_in[4];
    const float* otg       = (const float*)d_in[5];
    float* out = (float*)d_out;

    main_kernel<<<GRID1, 256>>>(logits, labels, olg, otg);
    batch_kernel<<<32, 256>>>(attract, existence, out, out_size);
}

// round 11
// speedup vs baseline: 1.4408x; 1.2121x over previous
#include <cuda_runtime.h>
#include <cuda_bf16.h>
#include <cstddef>

// B=32, T=32768, K=N=8, D=256
// Round-3 champion structure + dual-stream mma (2 independent row-streams
// per warp per iteration -> 2x load-level parallelism).
//   nlp = softplus(-x); p2 = sigmoid(x)^2
//   u = 4*nlp - x ; w = p2*x
//   A[k][n] = sum u*y ; W[k][n] = sum w*y   (mma.m16n8k16 bf16, u/w rows stacked)
//   S1[k] = sum (nlp+x) ; S2[k] = sum p2*(nlp+0.9x)
//   cost = (S1+A)/T ; assign_k = 0.75*(S2[k] - 0.8*W[k][col_k])

#define FULLMASK 0xffffffffu
#define CHUNKS 16
#define TPB_T 2048
#define SLOT 145   // 64 A + 64 W + 8 S1 + 8 S2 + 1 overlap

__device__ float gPart[32 * CHUNKS * SLOT];
__device__ float gTotal;
__device__ unsigned gCount;

__device__ __forceinline__ unsigned pk(float hi, float lo) {
    unsigned r;
    asm("cvt.rn.bf16x2.f32 %0, %1, %2;" : "=r"(r) : "f"(hi), "f"(lo));
    return r;
}

__device__ __forceinline__ void procE(float x, float& u, float& w,
                                      float& s1, float& s2) {
    float e = __expf(-x);
    float tt = 1.f + e;
    float nlp = __logf(tt);
    float r;
    asm("rcp.approx.ftz.f32 %0, %1;" : "=f"(r) : "f"(tt));
    float p2 = r * r;                     // sigmoid(x)^2
    u = fmaf(4.f, nlp, -x);
    w = p2 * x;
    s1 += nlp + x;
    s2 = fmaf(p2, fmaf(0.9f, x, nlp), s2);
}

__global__ void __launch_bounds__(256, 4)
main_kernel(const float* __restrict__ logits, const float* __restrict__ labels,
            const float* __restrict__ olg, const float* __restrict__ otg) {
    __shared__ float sAcc[SLOT];
    const int tid = threadIdx.x;
    if (tid < SLOT) sAcc[tid] = 0.f;
    if (blockIdx.x == 0 && blockIdx.y == 0 && tid == 0) { gTotal = 0.f; gCount = 0u; }
    __syncthreads();

    const int b = blockIdx.y, c = blockIdx.x;
    const int t0 = c * TPB_T;
    const float* lg = logits + (size_t)b * 32768 * 8;
    const float* yb = labels + (size_t)b * 32768 * 8;

    // ---- overlap MSE (coalesced float4) ----
    const float* ob = olg + (size_t)b * 32768 + t0;
    const float* tb = otg + (size_t)b * 32768 + t0;
    float ov = 0.f;
    for (int i = tid; i < TPB_T / 4; i += 256) {
        float4 o4 = reinterpret_cast<const float4*>(ob)[i];
        float4 t4 = reinterpret_cast<const float4*>(tb)[i];
        float d0 = o4.x - t4.x, d1 = o4.y - t4.y;
        float d2 = o4.z - t4.z, d3 = o4.w - t4.w;
        ov = fmaf(d0, d0, fmaf(d1, d1, fmaf(d2, d2, fmaf(d3, d3, ov))));
    }

    // ---- dual-stream mma: warp covers 256 t's; stream A rows [0,128),
    //      stream B rows [128,256), interleaved per iteration ----
    const int wrp = tid >> 5, l = tid & 31;
    const int gid = l >> 2, tg = l & 3;
    const int tw = t0 + wrp * 256;
    const float* xp = lg + (size_t)tw * 8 + gid;
    const float* yp = yb + (size_t)tw * 8 + gid;
    const int o0 = 16 * tg, o1 = o0 + 8, o2 = o0 + 64, o3 = o0 + 72;

    float a0 = 0.f, a1 = 0.f, a2 = 0.f, a3 = 0.f;   // stream A accum
    float e0 = 0.f, e1 = 0.f, e2 = 0.f, e3 = 0.f;   // stream B accum
    float s1 = 0.f, s2 = 0.f;

#pragma unroll 2
    for (int i = 0; i < 8; i++) {
        const int base = i * 128;
        // front-batched loads: 16 independent LDG
        float xA0 = xp[base + o0],        xA1 = xp[base + o1];
        float xA2 = xp[base + o2],        xA3 = xp[base + o3];
        float xB0 = xp[base + 1024 + o0], xB1 = xp[base + 1024 + o1];
        float xB2 = xp[base + 1024 + o2], xB3 = xp[base + 1024 + o3];
        float yA0 = yp[base + o0],        yA1 = yp[base + o1];
        float yA2 = yp[base + o2],        yA3 = yp[base + o3];
        float yB0 = yp[base + 1024 + o0], yB1 = yp[base + 1024 + o1];
        float yB2 = yp[base + 1024 + o2], yB3 = yp[base + 1024 + o3];

        float uA0, uA1, uA2, uA3, wA0, wA1, wA2, wA3;
        float uB0, uB1, uB2, uB3, wB0, wB1, wB2, wB3;
        procE(xA0, uA0, wA0, s1, s2);
        procE(xB0, uB0, wB0, s1, s2);
        procE(xA1, uA1, wA1, s1, s2);
        procE(xB1, uB1, wB1, s1, s2);
        procE(xA2, uA2, wA2, s1, s2);
        procE(xB2, uB2, wB2, s1, s2);
        procE(xA3, uA3, wA3, s1, s2);
        procE(xB3, uB3, wB3, s1, s2);

        unsigned fA0 = pk(uA1, uA0), fA1 = pk(wA1, wA0);
        unsigned fA2 = pk(uA3, uA2), fA3 = pk(wA3, wA2);
        unsigned gA0 = pk(yA1, yA0), gA1 = pk(yA3, yA2);
        asm("mma.sync.aligned.m16n8k16.row.col.f32.bf16.bf16.f32 "
            "{%0,%1,%2,%3}, {%4,%5,%6,%7}, {%8,%9}, {%0,%1,%2,%3};"
            : "+f"(a0), "+f"(a1), "+f"(a2), "+f"(a3)
            : "r"(fA0), "r"(fA1), "r"(fA2), "r"(fA3), "r"(gA0), "r"(gA1));

        unsigned fB0 = pk(uB1, uB0), fB1 = pk(wB1, wB0);
        unsigned fB2 = pk(uB3, uB2), fB3 = pk(wB3, wB2);
        unsigned gB0 = pk(yB1, yB0), gB1 = pk(yB3, yB2);
        asm("mma.sync.aligned.m16n8k16.row.col.f32.bf16.bf16.f32 "
            "{%0,%1,%2,%3}, {%4,%5,%6,%7}, {%8,%9}, {%0,%1,%2,%3};"
            : "+f"(e0), "+f"(e1), "+f"(e2), "+f"(e3)
            : "r"(fB0), "r"(fB1), "r"(fB2), "r"(fB3), "r"(gB0), "r"(gB1));
    }

    float c0 = a0 + e0, c1 = a1 + e1, c2 = a2 + e2, c3 = a3 + e3;

    // s1/s2: reduce across the 4 lanes of each gid group
    s1 += __shfl_xor_sync(FULLMASK, s1, 1);
    s1 += __shfl_xor_sync(FULLMASK, s1, 2);
    s2 += __shfl_xor_sync(FULLMASK, s2, 1);
    s2 += __shfl_xor_sync(FULLMASK, s2, 2);
#pragma unroll
    for (int off = 16; off >= 1; off >>= 1) ov += __shfl_down_sync(FULLMASK, ov, off);

    // C frag: c0=(gid,2tg) c1=(gid,2tg+1) rows 0-7 = A ; c2,c3 rows 8-15 = W
    atomicAdd(&sAcc[gid * 8 + 2 * tg],          c0);
    atomicAdd(&sAcc[gid * 8 + 2 * tg + 1],      c1);
    atomicAdd(&sAcc[64 + gid * 8 + 2 * tg],     c2);
    atomicAdd(&sAcc[64 + gid * 8 + 2 * tg + 1], c3);
    if (tg == 0) {
        atomicAdd(&sAcc[128 + gid], s1);
        atomicAdd(&sAcc[136 + gid], s2);
    }
    if (l == 0) atomicAdd(&sAcc[144], ov);
    __syncthreads();

    if (tid < SLOT) gPart[(b * CHUNKS + c) * SLOT + tid] = sAcc[tid];
}

// Per-batch: chunk reduce + gram + subset-DP assignment + existence; last block
// folds everything into the scalar output. (Round-3 validated.)
__global__ void __launch_bounds__(256)
batch_kernel(const float* __restrict__ att, const float* __restrict__ exist,
             float* __restrict__ out, int out_size) {
    __shared__ float red[SLOT];
    __shared__ float rb[37];     // 36 gram upper-tri + [36] existence sum
    __shared__ float csh[64];
    __shared__ float dp[256];
    __shared__ int   ch[256];
    __shared__ int   sLast;
    __shared__ float sTot;
    const int b = blockIdx.x, tid = threadIdx.x;

    if (tid < SLOT) {
        float s = 0.f;
#pragma unroll
        for (int c = 0; c < CHUNKS; c++) s += gPart[(b * CHUNKS + c) * SLOT + tid];
        red[tid] = s;
    }
    if (tid < 37) rb[tid] = 0.f;
    if (tid == 0) { dp[0] = 0.f; sLast = 0; }
    __syncthreads();

    if (tid < 64) {
        int k = tid >> 3;
        float cc = (red[128 + k] + red[tid]) * (1.f / 32768.f);
        if (!(fabsf(cc) <= 1e30f)) cc = 100.f;
        csh[tid] = cc;
    }
    if (tid < 8) {
        float e  = exist[b * 8 + tid];
        float ll = __logf(1.f + __expf(-fabsf(e)));
        float spn = ll + fmaxf(-e, 0.f);
        float spp = ll + fmaxf(e, 0.f);
        atomicAdd(&rb[36], 4.5f * spn + 0.1f * spp);
    }

    // attractor gram: thread = dim d (256 dims, fully parallel)
    const float* ab = att + (size_t)b * 8 * 256;
    float a[8];
#pragma unroll
    for (int k = 0; k < 8; k++) a[k] = ab[k * 256 + tid];
    float cp[36];
    {
        int idx = 0;
#pragma unroll
        for (int k = 0; k < 8; k++)
#pragma unroll
            for (int j = k; j < 8; j++) cp[idx++] = a[k] * a[j];
    }
#pragma unroll
    for (int off = 16; off >= 1; off >>= 1)
#pragma unroll
        for (int i = 0; i < 36; i++) cp[i] += __shfl_down_sync(FULLMASK, cp[i], off);
    if ((tid & 31) == 0)
#pragma unroll
        for (int i = 0; i < 36; i++) atomicAdd(&rb[i], cp[i]);

    // subset-DP exact assignment (level-synchronous over popcount)
    for (int r = 1; r <= 8; r++) {
        __syncthreads();
        int m = tid;
        if (m >= 1 && m < 256 && __popc(m) == r) {
            float best = 1e30f; int bn = 0;
#pragma unroll
            for (int n = 0; n < 8; n++) {
                if (m & (1 << n)) {
                    float v = dp[m ^ (1 << n)] + csh[(r - 1) * 8 + n];
                    if (v < best) { best = v; bn = n; }
                }
            }
            dp[m] = best; ch[m] = bn;
        }
    }
    __syncthreads();

    if (tid == 0) {
        float nrm[8]; int di = 0;
        for (int k = 0; k < 8; k++) { nrm[k] = fmaxf(sqrtf(rb[di]), 1e-12f); di += 8 - k; }
        float ortho = 0.f, contr = 0.f; int idx = 0;
        for (int k = 0; k < 8; k++)
            for (int j = k; j < 8; j++) {
                float s = rb[idx] / (nrm[k] * nrm[j]);
                if (j == k) { float d = s - 1.f; ortho += d * d; }
                else { ortho += 2.f * s * s; contr += 2.f * fmaxf(s + 0.5f, 0.f); }
                idx++;
            }

        int mask = 255, col[8];
        for (int r = 7; r >= 0; --r) { int n = ch[mask]; col[r] = n; mask ^= (1 << n); }
        float asn = 0.f;
        for (int k = 0; k < 8; k++)
            asn += 0.75f * (red[136 + k] - 0.8f * red[64 + k * 8 + col[k]]);

        float contrib = asn * (1.f / 8388608.f)          // assign mean (B*T*K)
                      + rb[36] * (1.f / 256.f)           // exist mean
                      + 0.1f * ortho * (1.f / 2048.f)    // ortho mean
                      + 0.1f * contr * (1.f / 1792.f)    // contrast
                      + 0.5f * red[144] * (1.f / 1048576.f); // overlap mean
        atomicAdd(&gTotal, contrib);
        __threadfence();
        unsigned old = atomicAdd(&gCount, 1u);
        if (old == 31u) { sLast = 1; sTot = atomicAdd(&gTotal, 0.f); }
    }
    __syncthreads();
    if (sLast) {
        float t = sTot;
        for (int i = tid; i < out_size; i += blockDim.x) out[i] = t;
    }
}

extern "C" void kernel_launch(void* const* d_in, const int* in_sizes, int n_in,
                              void* d_out, int out_size) {
    const float* logits    = (const float*)d_in[0];
    const float* existence = (const float*)d_in[1];
    const float* attract   = (const float*)d_in[2];
    const float* labels    = (const float*)d_in[3];
    const float* olg       = (const float*)d_in[4];
    const float* otg       = (const float*)d_in[5];
    float* out = (float*)d_out;

    dim3 grid(CHUNKS, 32);
    main_kernel<<<grid, 256>>>(logits, labels, olg, otg);
    batch_kernel<<<32, 256>>>(attract, existence, out, out_size);
}